// round 1
// baseline (speedup 1.0000x reference)
#include <cuda_runtime.h>
#include <cstdint>

#define Bsz 8
#define Tsz 4096
#define Dsz 1024
#define Msz (Bsz*Tsz)          // 32768 rows
#define CHUNKS 32
#define CLEN (Tsz/CHUNKS)      // 128

#define BM 128
#define BN 64
#define BK 32

// Scratch (device globals — no allocation allowed in kernel_launch)
__device__ float g_a[(size_t)Msz*Dsz];          // 128 MB
__device__ float g_b[(size_t)Msz*Dsz];          // 128 MB
__device__ float g_lsig[Dsz];
__device__ float g_P[Bsz*CHUNKS*Dsz];
__device__ float g_S[Bsz*CHUNKS*Dsz];
__device__ float g_h0[Bsz*CHUNKS*Dsz];

// ---------------------------------------------------------------------------
// Kernel 0: log_sigmoid(lambd), computed once (accurate path).
// ---------------------------------------------------------------------------
__global__ void lsig_kernel(const float* __restrict__ lambd) {
    int i = blockIdx.x * blockDim.x + threadIdx.x;
    if (i < Dsz) {
        float l = lambd[i];
        g_lsig[i] = -log1pf(expf(-l));   // log_sigmoid(l)
    }
}

// ---------------------------------------------------------------------------
// packed f32x2 helpers (sm_103a packed FP32 pipe — 2x FFMA throughput)
// ---------------------------------------------------------------------------
__device__ __forceinline__ unsigned long long pack2(float v) {
    unsigned long long r;
    asm("mov.b64 %0, {%1, %1};" : "=l"(r) : "f"(v));
    return r;
}
__device__ __forceinline__ void fma2(unsigned long long& acc,
                                     unsigned long long a,
                                     unsigned long long b) {
    asm("fma.rn.f32x2 %0, %1, %2, %0;" : "+l"(acc) : "l"(a), "l"(b));
}
__device__ __forceinline__ void unpack2(unsigned long long v, float& lo, float& hi) {
    asm("mov.b64 {%0, %1}, %2;" : "=f"(lo), "=f"(hi) : "l"(v));
}

// ---------------------------------------------------------------------------
// Kernel 1: dual fused GEMM (r and i gates share the x tile) + gate epilogue.
// Computes z_r = x @ W_r^T, z_i = x @ W_i^T for a [128 x 64] output tile,
// then a = exp(8*sigmoid(z_r)*logsig(lambd)), b = sqrt(1-a^2)*sigmoid(z_i)*x.
// Writes a, b to scratch.
// ---------------------------------------------------------------------------
__global__ __launch_bounds__(256, 2)
void gemm_gates(const float* __restrict__ x,
                const float* __restrict__ Wr,
                const float* __restrict__ Wi) {
    __shared__ __align__(16) float xs [BK][BM + 4];
    __shared__ __align__(16) float wrs[BK][BN + 2];
    __shared__ __align__(16) float wis[BK][BN + 2];

    const int tid = threadIdx.x;
    const int tx  = tid & 15;   // n direction: 16 groups of 4
    const int ty  = tid >> 4;   // m direction: 16 groups of 8
    const int m0  = blockIdx.y * BM;
    const int n0  = blockIdx.x * BN;

    unsigned long long ar[8][2] = {};   // packed f32x2 accumulators (r gate)
    unsigned long long ai[8][2] = {};   // packed f32x2 accumulators (i gate)

    for (int k0 = 0; k0 < Dsz; k0 += BK) {
        // load x tile [128 x 32] -> xs[k][m]
        #pragma unroll
        for (int l = 0; l < 4; l++) {
            int idx = tid + l * 256;
            int row = idx >> 3;
            int c4  = (idx & 7) << 2;
            float4 v = *(const float4*)(x + (size_t)(m0 + row) * Dsz + k0 + c4);
            xs[c4+0][row] = v.x; xs[c4+1][row] = v.y;
            xs[c4+2][row] = v.z; xs[c4+3][row] = v.w;
        }
        // load W_r / W_i tiles [64 x 32] -> ws[k][n]
        #pragma unroll
        for (int l = 0; l < 2; l++) {
            int idx = tid + l * 256;
            int row = idx >> 3;
            int c4  = (idx & 7) << 2;
            float4 vr = *(const float4*)(Wr + (size_t)(n0 + row) * Dsz + k0 + c4);
            wrs[c4+0][row] = vr.x; wrs[c4+1][row] = vr.y;
            wrs[c4+2][row] = vr.z; wrs[c4+3][row] = vr.w;
            float4 vi = *(const float4*)(Wi + (size_t)(n0 + row) * Dsz + k0 + c4);
            wis[c4+0][row] = vi.x; wis[c4+1][row] = vi.y;
            wis[c4+2][row] = vi.z; wis[c4+3][row] = vi.w;
        }
        __syncthreads();

        #pragma unroll
        for (int k = 0; k < BK; k++) {
            unsigned long long wr0 = *(const unsigned long long*)&wrs[k][tx*4];
            unsigned long long wr1 = *(const unsigned long long*)&wrs[k][tx*4+2];
            unsigned long long wi0 = *(const unsigned long long*)&wis[k][tx*4];
            unsigned long long wi1 = *(const unsigned long long*)&wis[k][tx*4+2];
            float4 xa = *(const float4*)&xs[k][ty*8];
            float4 xb = *(const float4*)&xs[k][ty*8+4];
            float xv[8] = {xa.x, xa.y, xa.z, xa.w, xb.x, xb.y, xb.z, xb.w};
            #pragma unroll
            for (int i = 0; i < 8; i++) {
                unsigned long long xp = pack2(xv[i]);
                fma2(ar[i][0], xp, wr0);
                fma2(ar[i][1], xp, wr1);
                fma2(ai[i][0], xp, wi0);
                fma2(ai[i][1], xp, wi1);
            }
        }
        __syncthreads();
    }

    // epilogue: gates -> (a, b)
    float4 lsv = *(const float4*)&g_lsig[n0 + tx*4];
    float ls[4] = {lsv.x, lsv.y, lsv.z, lsv.w};

    #pragma unroll
    for (int i = 0; i < 8; i++) {
        int m = m0 + ty*8 + i;
        float4 xv4 = *(const float4*)(x + (size_t)m * Dsz + n0 + tx*4);
        float xq[4] = {xv4.x, xv4.y, xv4.z, xv4.w};
        float zr[4], zi[4];
        unpack2(ar[i][0], zr[0], zr[1]);
        unpack2(ar[i][1], zr[2], zr[3]);
        unpack2(ai[i][0], zi[0], zi[1]);
        unpack2(ai[i][1], zi[2], zi[3]);
        float av[4], bv[4];
        #pragma unroll
        for (int j = 0; j < 4; j++) {
            float r  = __fdividef(1.f, 1.f + __expf(-zr[j]));
            float ig = __fdividef(1.f, 1.f + __expf(-zi[j]));
            float la = 8.f * r * ls[j];
            float a  = __expf(la);
            float om = fmaxf(1.f - a * a, 0.f);
            av[j] = a;
            bv[j] = sqrtf(om) * ig * xq[j];
        }
        size_t off = (size_t)m * Dsz + n0 + tx*4;
        *(float4*)&g_a[off] = make_float4(av[0], av[1], av[2], av[3]);
        *(float4*)&g_b[off] = make_float4(bv[0], bv[1], bv[2], bv[3]);
    }
}

// ---------------------------------------------------------------------------
// Kernel 2: per-chunk reduce: P = prod(a), S = local scan end (h0 = 0)
// thread -> (batch, chunk, channel); consecutive threads = consecutive e
// ---------------------------------------------------------------------------
__global__ void scan_reduce() {
    int g = blockIdx.x * blockDim.x + threadIdx.x;   // 262144 threads
    int e = g & (Dsz - 1);
    int rest = g >> 10;
    int c = rest & (CHUNKS - 1);
    int b = rest >> 5;
    size_t base = ((size_t)(b * Tsz + c * CLEN)) * Dsz + e;
    float P = 1.f, H = 0.f;
    #pragma unroll 4
    for (int t = 0; t < CLEN; t++) {
        float a  = g_a[base + (size_t)t * Dsz];
        float bb = g_b[base + (size_t)t * Dsz];
        H = fmaf(a, H, bb);
        P *= a;
    }
    int idx = (b * CHUNKS + c) * Dsz + e;
    g_P[idx] = P;
    g_S[idx] = H;
}

// ---------------------------------------------------------------------------
// Kernel 3: sequential scan across chunks (tiny: 8192 channels x 32 chunks)
// ---------------------------------------------------------------------------
__global__ void scan_chunks() {
    int g = blockIdx.x * blockDim.x + threadIdx.x;   // 8192 threads
    int e = g & (Dsz - 1);
    int b = g >> 10;
    float h = 0.f;
    #pragma unroll
    for (int c = 0; c < CHUNKS; c++) {
        int idx = (b * CHUNKS + c) * Dsz + e;
        g_h0[idx] = h;
        h = fmaf(g_P[idx], h, g_S[idx]);
    }
}

// ---------------------------------------------------------------------------
// Kernel 4: apply — rerun local scan seeded with chunk prefix, write h out
// ---------------------------------------------------------------------------
__global__ void scan_apply(float* __restrict__ out) {
    int g = blockIdx.x * blockDim.x + threadIdx.x;
    int e = g & (Dsz - 1);
    int rest = g >> 10;
    int c = rest & (CHUNKS - 1);
    int b = rest >> 5;
    size_t base = ((size_t)(b * Tsz + c * CLEN)) * Dsz + e;
    float h = g_h0[(b * CHUNKS + c) * Dsz + e];
    #pragma unroll 4
    for (int t = 0; t < CLEN; t++) {
        float a  = g_a[base + (size_t)t * Dsz];
        float bb = g_b[base + (size_t)t * Dsz];
        h = fmaf(a, h, bb);
        out[base + (size_t)t * Dsz] = h;
    }
}

// ---------------------------------------------------------------------------
extern "C" void kernel_launch(void* const* d_in, const int* in_sizes, int n_in,
                              void* d_out, int out_size) {
    (void)in_sizes; (void)n_in; (void)out_size;
    const float* x     = (const float*)d_in[0];
    const float* Wr    = (const float*)d_in[1];
    const float* Wi    = (const float*)d_in[2];
    const float* lambd = (const float*)d_in[3];
    float* out = (float*)d_out;

    lsig_kernel<<<4, 256>>>(lambd);

    dim3 grid(Dsz / BN, Msz / BM);   // (16, 256)
    gemm_gates<<<grid, 256>>>(x, Wr, Wi);

    scan_reduce<<<(Bsz * CHUNKS * Dsz) / 256, 256>>>();   // 1024 blocks
    scan_chunks<<<(Bsz * Dsz) / 256, 256>>>();            // 32 blocks
    scan_apply<<<(Bsz * CHUNKS * Dsz) / 256, 256>>>(out); // 1024 blocks
}

// round 3
// speedup vs baseline: 1.9468x; 1.9468x over previous
#include <cuda_runtime.h>
#include <cstdint>

#define Bsz 8
#define Tsz 4096
#define Dsz 1024
#define Msz (Bsz*Tsz)          // 32768 rows
#define Nsz 2048               // both gates concatenated
#define CHUNKS 32
#define CLEN (Tsz/CHUNKS)      // 128

#define BM 128
#define BN 64
#define BK 32
#define APAD 36                // smem row stride in floats (16B-aligned, conflict-free)
#define A_FLOATS (BM*APAD)     // 4608
#define B_FLOATS (BN*APAD)     // 2304
#define STAGE_FLOATS (A_FLOATS + B_FLOATS)   // 6912
#define SMEM_BYTES (2*STAGE_FLOATS*4)        // 55296

// ---------------- scratch ----------------------------------------------------
__device__ float g_a  [(size_t)Msz*Dsz];      // a gate (128 MB)
__device__ float g_b  [(size_t)Msz*Dsz];      // b' = sigmoid(zi)*x (128 MB)
__device__ float g_xt [(size_t)Msz*Dsz];      // tf32-rounded x (128 MB)
__device__ float g_wc [(size_t)Nsz*Dsz];      // tf32-rounded [Wr; Wi] (8 MB)
__device__ float g_lsig[Dsz];
__device__ float g_P[Bsz*CHUNKS*Dsz];
__device__ float g_S[Bsz*CHUNKS*Dsz];
__device__ float g_h0[Bsz*CHUNKS*Dsz];

// ---------------- helpers -----------------------------------------------------
__device__ __forceinline__ uint32_t smem_u32(const void* p) {
    uint32_t a;
    asm("{ .reg .u64 t; cvta.to.shared.u64 t, %1; cvt.u32.u64 %0, t; }"
        : "=r"(a) : "l"(p));
    return a;
}
__device__ __forceinline__ void cp16(uint32_t saddr, const void* gaddr) {
    asm volatile("cp.async.cg.shared.global [%0], [%1], 16;"
                 :: "r"(saddr), "l"(gaddr));
}
__device__ __forceinline__ float tf32_rn(float v) {
    uint32_t o;
    asm("cvt.rn.tf32.f32 %0, %1;" : "=r"(o) : "f"(v));
    return __uint_as_float(o);
}
__device__ __forceinline__ void mma_tf32(float* d, const uint32_t* a, const uint32_t* b) {
    asm volatile(
        "mma.sync.aligned.m16n8k8.row.col.f32.tf32.tf32.f32 "
        "{%0,%1,%2,%3}, {%4,%5,%6,%7}, {%8,%9}, {%0,%1,%2,%3};"
        : "+f"(d[0]), "+f"(d[1]), "+f"(d[2]), "+f"(d[3])
        : "r"(a[0]), "r"(a[1]), "r"(a[2]), "r"(a[3]), "r"(b[0]), "r"(b[1]));
}

// ---------------- prep kernels -------------------------------------------------
__global__ void lsig_kernel(const float* __restrict__ lambd) {
    int i = blockIdx.x * blockDim.x + threadIdx.x;
    if (i < Dsz) g_lsig[i] = -log1pf(expf(-lambd[i]));
}
__global__ void prep_x(const float* __restrict__ x) {
    size_t i = ((size_t)blockIdx.x * 256 + threadIdx.x) * 4;
    float4 v = *(const float4*)(x + i);
    *(float4*)(g_xt + i) = make_float4(tf32_rn(v.x), tf32_rn(v.y), tf32_rn(v.z), tf32_rn(v.w));
}
__global__ void prep_w(const float* __restrict__ wr, const float* __restrict__ wi) {
    int row = blockIdx.x;                      // 0..2047
    const float* src = (row < Dsz) ? (wr + (size_t)row * Dsz)
                                   : (wi + (size_t)(row - Dsz) * Dsz);
    float* dst = g_wc + (size_t)row * Dsz;
    int c = threadIdx.x * 4;
    float4 v = *(const float4*)(src + c);
    *(float4*)(dst + c) = make_float4(tf32_rn(v.x), tf32_rn(v.y), tf32_rn(v.z), tf32_rn(v.w));
}

// ---------------- GEMM (tf32 mma.sync) + fused gate epilogue -------------------
__global__ __launch_bounds__(256, 2)
void gemm_tc(const float* __restrict__ x) {
    extern __shared__ __align__(16) float sm[];
    const int tid = threadIdx.x;
    const int wid = tid >> 5, l = tid & 31;
    const int gq  = l >> 2, tq = l & 3;     // quad group / thread-in-group
    const int warp_m = wid & 3;             // 0..3 -> 32-row slices
    const int warp_n = wid >> 2;            // 0..1 -> 32-col slices
    const int m0 = blockIdx.y * BM;
    const int n0 = blockIdx.x * BN;         // global n in [0, 2048)

    float acc[2][4][4];
    #pragma unroll
    for (int mt = 0; mt < 2; mt++)
        #pragma unroll
        for (int nt = 0; nt < 4; nt++)
            #pragma unroll
            for (int q = 0; q < 4; q++) acc[mt][nt][q] = 0.f;

    uint32_t sA[2], sB[2];
    sA[0] = smem_u32(sm);
    sA[1] = sA[0] + STAGE_FLOATS * 4;
    sB[0] = sA[0] + A_FLOATS * 4;
    sB[1] = sA[1] + A_FLOATS * 4;

    // --- stage loader (cp.async) ---
    auto load_stage = [&](int st, int k0) {
        const float* ag = g_xt + (size_t)m0 * Dsz + k0 * BK;
        #pragma unroll
        for (int i = 0; i < 4; i++) {            // A: 128 rows x 8 chunks
            int idx = tid + i * 256;
            int r = idx >> 3, c = idx & 7;
            cp16(sA[st] + (r * APAD + c * 4) * 4, ag + (size_t)r * Dsz + c * 4);
        }
        const float* bg = g_wc + (size_t)n0 * Dsz + k0 * BK;
        #pragma unroll
        for (int i = 0; i < 2; i++) {            // B: 64 rows x 8 chunks
            int idx = tid + i * 256;
            int r = idx >> 3, c = idx & 7;
            cp16(sB[st] + (r * APAD + c * 4) * 4, bg + (size_t)r * Dsz + c * 4);
        }
        asm volatile("cp.async.commit_group;" ::: "memory");
    };

    load_stage(0, 0);

    #pragma unroll 1
    for (int k0 = 0; k0 < Dsz / BK; k0++) {
        int cur = k0 & 1;
        if (k0 < Dsz / BK - 1) {
            load_stage(cur ^ 1, k0 + 1);
            asm volatile("cp.async.wait_group 1;" ::: "memory");
        } else {
            asm volatile("cp.async.wait_group 0;" ::: "memory");
        }
        __syncthreads();

        const float* As = sm + cur * STAGE_FLOATS;
        const float* Bs = As + A_FLOATS;
        #pragma unroll
        for (int kk = 0; kk < 4; kk++) {
            int kb = kk * 8 + tq;
            uint32_t af[2][4], bf[4][2];
            #pragma unroll
            for (int mt = 0; mt < 2; mt++) {
                const float* ap = As + (warp_m * 32 + mt * 16 + gq) * APAD + kb;
                af[mt][0] = __float_as_uint(ap[0]);
                af[mt][1] = __float_as_uint(ap[8 * APAD]);
                af[mt][2] = __float_as_uint(ap[4]);
                af[mt][3] = __float_as_uint(ap[8 * APAD + 4]);
            }
            #pragma unroll
            for (int nt = 0; nt < 4; nt++) {
                const float* bp = Bs + (warp_n * 32 + nt * 8 + gq) * APAD + kb;
                bf[nt][0] = __float_as_uint(bp[0]);
                bf[nt][1] = __float_as_uint(bp[4]);
            }
            #pragma unroll
            for (int mt = 0; mt < 2; mt++)
                #pragma unroll
                for (int nt = 0; nt < 4; nt++)
                    mma_tf32(acc[mt][nt], af[mt], bf[nt]);
        }
        __syncthreads();
    }

    // --- epilogue ---
    // d mapping: c0,c1 -> row = base+gq,   cols 2tq, 2tq+1
    //            c2,c3 -> row = base+gq+8, cols 2tq, 2tq+1
    const bool is_r = (n0 < Dsz);
    #pragma unroll
    for (int mt = 0; mt < 2; mt++) {
        #pragma unroll
        for (int nt = 0; nt < 4; nt++) {
            int col = n0 + warp_n * 32 + nt * 8 + 2 * tq;       // global n
            #pragma unroll
            for (int h = 0; h < 2; h++) {                       // c01 / c23
                int row = m0 + warp_m * 32 + mt * 16 + gq + 8 * h;
                float z0 = acc[mt][nt][2 * h + 0];
                float z1 = acc[mt][nt][2 * h + 1];
                if (is_r) {
                    float ls0 = __ldg(&g_lsig[col]);
                    float ls1 = __ldg(&g_lsig[col + 1]);
                    float r0 = __fdividef(1.f, 1.f + __expf(-z0));
                    float r1 = __fdividef(1.f, 1.f + __expf(-z1));
                    float2 av = make_float2(__expf(8.f * r0 * ls0),
                                            __expf(8.f * r1 * ls1));
                    *(float2*)(g_a + (size_t)row * Dsz + col) = av;
                } else {
                    int ce = col - Dsz;
                    float2 xv = *(const float2*)(x + (size_t)row * Dsz + ce);
                    float i0 = __fdividef(1.f, 1.f + __expf(-z0));
                    float i1 = __fdividef(1.f, 1.f + __expf(-z1));
                    float2 bv = make_float2(i0 * xv.x, i1 * xv.y);
                    *(float2*)(g_b + (size_t)row * Dsz + ce) = bv;
                }
            }
        }
    }
}

// ---------------- scan kernels -------------------------------------------------
// b_t = sqrt(max(1 - a^2, 0)) * b'  recomputed identically in both passes.
__global__ void scan_reduce() {
    int g = blockIdx.x * blockDim.x + threadIdx.x;
    int e = g & (Dsz - 1);
    int rest = g >> 10;
    int c = rest & (CHUNKS - 1);
    int b = rest >> 5;
    size_t base = ((size_t)(b * Tsz + c * CLEN)) * Dsz + e;
    float P = 1.f, H = 0.f;
    #pragma unroll 4
    for (int t = 0; t < CLEN; t++) {
        float a  = g_a[base + (size_t)t * Dsz];
        float bp = g_b[base + (size_t)t * Dsz];
        float bb = sqrtf(fmaxf(1.f - a * a, 0.f)) * bp;
        H = fmaf(a, H, bb);
        P *= a;
    }
    int idx = (b * CHUNKS + c) * Dsz + e;
    g_P[idx] = P;
    g_S[idx] = H;
}

__global__ void scan_chunks() {
    int g = blockIdx.x * blockDim.x + threadIdx.x;
    int e = g & (Dsz - 1);
    int b = g >> 10;
    float h = 0.f;
    #pragma unroll
    for (int c = 0; c < CHUNKS; c++) {
        int idx = (b * CHUNKS + c) * Dsz + e;
        g_h0[idx] = h;
        h = fmaf(g_P[idx], h, g_S[idx]);
    }
}

__global__ void scan_apply(float* __restrict__ out) {
    int g = blockIdx.x * blockDim.x + threadIdx.x;
    int e = g & (Dsz - 1);
    int rest = g >> 10;
    int c = rest & (CHUNKS - 1);
    int b = rest >> 5;
    size_t base = ((size_t)(b * Tsz + c * CLEN)) * Dsz + e;
    float h = g_h0[(b * CHUNKS + c) * Dsz + e];
    #pragma unroll 4
    for (int t = 0; t < CLEN; t++) {
        float a  = g_a[base + (size_t)t * Dsz];
        float bp = g_b[base + (size_t)t * Dsz];
        float bb = sqrtf(fmaxf(1.f - a * a, 0.f)) * bp;
        h = fmaf(a, h, bb);
        out[base + (size_t)t * Dsz] = h;
    }
}

// ---------------- launch --------------------------------------------------------
extern "C" void kernel_launch(void* const* d_in, const int* in_sizes, int n_in,
                              void* d_out, int out_size) {
    (void)in_sizes; (void)n_in; (void)out_size;
    const float* x     = (const float*)d_in[0];
    const float* Wr    = (const float*)d_in[1];
    const float* Wi    = (const float*)d_in[2];
    const float* lambd = (const float*)d_in[3];
    float* out = (float*)d_out;

    static bool attr_set = false;
    if (!attr_set) {
        cudaFuncSetAttribute(gemm_tc, cudaFuncAttributeMaxDynamicSharedMemorySize,
                             SMEM_BYTES);
        attr_set = true;
    }

    lsig_kernel<<<4, 256>>>(lambd);
    prep_x<<<(Msz * Dsz) / 1024, 256>>>(x);
    prep_w<<<Nsz, 256>>>(Wr, Wi);

    dim3 grid(Nsz / BN, Msz / BM);   // (32, 256)
    gemm_tc<<<grid, 256, SMEM_BYTES>>>(x);

    scan_reduce<<<(Bsz * CHUNKS * Dsz) / 256, 256>>>();
    scan_chunks<<<(Bsz * Dsz) / 256, 256>>>();
    scan_apply<<<(Bsz * CHUNKS * Dsz) / 256, 256>>>(out);
}

// round 4
// speedup vs baseline: 2.1981x; 1.1290x over previous
#include <cuda_runtime.h>
#include <cstdint>

#define Bsz 8
#define Tsz 4096
#define Dsz 1024
#define Msz (Bsz*Tsz)          // 32768 rows
#define Nsz 2048               // both gates concatenated
#define CHUNKS 32
#define CLEN (Tsz/CHUNKS)      // 128

#define BM 128
#define BN 64
#define BK 32
#define NSTAGE 3
#define APAD 36                // smem row stride in floats (16B-aligned, conflict-free)
#define A_FLOATS (BM*APAD)     // 4608
#define B_FLOATS (BN*APAD)     // 2304
#define STAGE_FLOATS (A_FLOATS + B_FLOATS)   // 6912
#define SMEM_BYTES (NSTAGE*STAGE_FLOATS*4)   // 82944

// ---------------- scratch ----------------------------------------------------
__device__ float g_a  [(size_t)Msz*Dsz];      // a gate (128 MB)
__device__ float g_b  [(size_t)Msz*Dsz];      // b' = sigmoid(zi)*x (128 MB)
__device__ float g_wc [(size_t)Nsz*Dsz];      // tf32-rounded [Wr; Wi] (8 MB)
__device__ float g_lsig[Dsz];
__device__ float g_P[Bsz*CHUNKS*Dsz];
__device__ float g_S[Bsz*CHUNKS*Dsz];
__device__ float g_h0[Bsz*CHUNKS*Dsz];

// ---------------- helpers -----------------------------------------------------
__device__ __forceinline__ uint32_t smem_u32(const void* p) {
    uint32_t a;
    asm("{ .reg .u64 t; cvta.to.shared.u64 t, %1; cvt.u32.u64 %0, t; }"
        : "=r"(a) : "l"(p));
    return a;
}
__device__ __forceinline__ void cp16(uint32_t saddr, const void* gaddr) {
    asm volatile("cp.async.cg.shared.global [%0], [%1], 16;"
                 :: "r"(saddr), "l"(gaddr));
}
__device__ __forceinline__ float tf32_rn(float v) {
    uint32_t o;
    asm("cvt.rn.tf32.f32 %0, %1;" : "=r"(o) : "f"(v));
    return __uint_as_float(o);
}
__device__ __forceinline__ void mma_tf32(float* d, const uint32_t* a, const uint32_t* b) {
    asm volatile(
        "mma.sync.aligned.m16n8k8.row.col.f32.tf32.tf32.f32 "
        "{%0,%1,%2,%3}, {%4,%5,%6,%7}, {%8,%9}, {%0,%1,%2,%3};"
        : "+f"(d[0]), "+f"(d[1]), "+f"(d[2]), "+f"(d[3])
        : "r"(a[0]), "r"(a[1]), "r"(a[2]), "r"(a[3]), "r"(b[0]), "r"(b[1]));
}

// ---------------- prep kernels -------------------------------------------------
__global__ void lsig_kernel(const float* __restrict__ lambd) {
    int i = blockIdx.x * blockDim.x + threadIdx.x;
    if (i < Dsz) g_lsig[i] = -log1pf(expf(-lambd[i]));
}
__global__ void prep_w(const float* __restrict__ wr, const float* __restrict__ wi) {
    int row = blockIdx.x;                      // 0..2047
    const float* src = (row < Dsz) ? (wr + (size_t)row * Dsz)
                                   : (wi + (size_t)(row - Dsz) * Dsz);
    float* dst = g_wc + (size_t)row * Dsz;
    int c = threadIdx.x * 4;
    float4 v = *(const float4*)(src + c);
    *(float4*)(dst + c) = make_float4(tf32_rn(v.x), tf32_rn(v.y), tf32_rn(v.z), tf32_rn(v.w));
}

// ---------------- GEMM (tf32 mma.sync) + fused gate epilogue -------------------
// A = x (raw f32; HW truncates to tf32), B = pre-rounded [Wr;Wi].
__global__ __launch_bounds__(256, 2)
void gemm_tc(const float* __restrict__ x) {
    extern __shared__ __align__(16) float sm[];
    const int tid = threadIdx.x;
    const int wid = tid >> 5, l = tid & 31;
    const int gq  = l >> 2, tq = l & 3;     // quad group / thread-in-group
    const int warp_m = wid & 3;             // 0..3 -> 32-row slices
    const int warp_n = wid >> 2;            // 0..1 -> 32-col slices
    const int m0 = blockIdx.y * BM;
    const int n0 = blockIdx.x * BN;         // global n in [0, 2048)

    float acc[2][4][4];
    #pragma unroll
    for (int mt = 0; mt < 2; mt++)
        #pragma unroll
        for (int nt = 0; nt < 4; nt++)
            #pragma unroll
            for (int q = 0; q < 4; q++) acc[mt][nt][q] = 0.f;

    const uint32_t s0 = smem_u32(sm);

    // --- stage loader (cp.async) ---
    auto load_stage = [&](int st, int k0) {
        uint32_t sA = s0 + st * STAGE_FLOATS * 4;
        uint32_t sB = sA + A_FLOATS * 4;
        const float* ag = x + (size_t)m0 * Dsz + k0 * BK;
        #pragma unroll
        for (int i = 0; i < 4; i++) {            // A: 128 rows x 8 chunks
            int idx = tid + i * 256;
            int r = idx >> 3, c = idx & 7;
            cp16(sA + (r * APAD + c * 4) * 4, ag + (size_t)r * Dsz + c * 4);
        }
        const float* bg = g_wc + (size_t)n0 * Dsz + k0 * BK;
        #pragma unroll
        for (int i = 0; i < 2; i++) {            // B: 64 rows x 8 chunks
            int idx = tid + i * 256;
            int r = idx >> 3, c = idx & 7;
            cp16(sB + (r * APAD + c * 4) * 4, bg + (size_t)r * Dsz + c * 4);
        }
        asm volatile("cp.async.commit_group;" ::: "memory");
    };

    load_stage(0, 0);
    load_stage(1, 1);

    #pragma unroll 1
    for (int k0 = 0; k0 < Dsz / BK; k0++) {
        int s = k0 % NSTAGE;
        if (k0 < Dsz / BK - 1)
            asm volatile("cp.async.wait_group 1;" ::: "memory");
        else
            asm volatile("cp.async.wait_group 0;" ::: "memory");
        __syncthreads();   // single barrier per iteration

        const float* As = sm + s * STAGE_FLOATS;
        const float* Bs = As + A_FLOATS;
        #pragma unroll
        for (int kk = 0; kk < 4; kk++) {
            int kb = kk * 8 + tq;
            uint32_t af[2][4], bf[4][2];
            #pragma unroll
            for (int mt = 0; mt < 2; mt++) {
                const float* ap = As + (warp_m * 32 + mt * 16 + gq) * APAD + kb;
                af[mt][0] = __float_as_uint(ap[0]);
                af[mt][1] = __float_as_uint(ap[8 * APAD]);
                af[mt][2] = __float_as_uint(ap[4]);
                af[mt][3] = __float_as_uint(ap[8 * APAD + 4]);
            }
            #pragma unroll
            for (int nt = 0; nt < 4; nt++) {
                const float* bp = Bs + (warp_n * 32 + nt * 8 + gq) * APAD + kb;
                bf[nt][0] = __float_as_uint(bp[0]);
                bf[nt][1] = __float_as_uint(bp[4]);
            }
            #pragma unroll
            for (int mt = 0; mt < 2; mt++)
                #pragma unroll
                for (int nt = 0; nt < 4; nt++)
                    mma_tf32(acc[mt][nt], af[mt], bf[nt]);
        }
        // load stage k0+2 into buffer (k0+2)%3 = (k0-1)%3: all warps passed the
        // top-of-iter barrier, which is after their iter k0-1 reads. Safe.
        if (k0 + 2 < Dsz / BK) load_stage((k0 + 2) % NSTAGE, k0 + 2);
    }

    // --- epilogue ---
    const bool is_r = (n0 < Dsz);
    #pragma unroll
    for (int mt = 0; mt < 2; mt++) {
        #pragma unroll
        for (int nt = 0; nt < 4; nt++) {
            int col = n0 + warp_n * 32 + nt * 8 + 2 * tq;       // global n
            #pragma unroll
            for (int h = 0; h < 2; h++) {                       // c01 / c23
                int row = m0 + warp_m * 32 + mt * 16 + gq + 8 * h;
                float z0 = acc[mt][nt][2 * h + 0];
                float z1 = acc[mt][nt][2 * h + 1];
                if (is_r) {
                    float ls0 = __ldg(&g_lsig[col]);
                    float ls1 = __ldg(&g_lsig[col + 1]);
                    float r0 = __fdividef(1.f, 1.f + __expf(-z0));
                    float r1 = __fdividef(1.f, 1.f + __expf(-z1));
                    float2 av = make_float2(__expf(8.f * r0 * ls0),
                                            __expf(8.f * r1 * ls1));
                    *(float2*)(g_a + (size_t)row * Dsz + col) = av;
                } else {
                    int ce = col - Dsz;
                    float2 xv = *(const float2*)(x + (size_t)row * Dsz + ce);
                    float i0 = __fdividef(1.f, 1.f + __expf(-z0));
                    float i1 = __fdividef(1.f, 1.f + __expf(-z1));
                    float2 bv = make_float2(i0 * xv.x, i1 * xv.y);
                    *(float2*)(g_b + (size_t)row * Dsz + ce) = bv;
                }
            }
        }
    }
}

// ---------------- scan kernels -------------------------------------------------
// b_t = sqrt(max(1 - a^2, 0)) * b'  recomputed identically in both passes.
__global__ void scan_reduce() {
    int g = blockIdx.x * blockDim.x + threadIdx.x;
    int e = g & (Dsz - 1);
    int rest = g >> 10;
    int c = rest & (CHUNKS - 1);
    int b = rest >> 5;
    size_t base = ((size_t)(b * Tsz + c * CLEN)) * Dsz + e;
    float P = 1.f, H = 0.f;
    #pragma unroll 4
    for (int t = 0; t < CLEN; t++) {
        float a  = g_a[base + (size_t)t * Dsz];
        float bp = g_b[base + (size_t)t * Dsz];
        float bb = sqrtf(fmaxf(1.f - a * a, 0.f)) * bp;
        H = fmaf(a, H, bb);
        P *= a;
    }
    int idx = (b * CHUNKS + c) * Dsz + e;
    g_P[idx] = P;
    g_S[idx] = H;
}

__global__ void scan_chunks() {
    int g = blockIdx.x * blockDim.x + threadIdx.x;
    int e = g & (Dsz - 1);
    int b = g >> 10;
    float h = 0.f;
    #pragma unroll
    for (int c = 0; c < CHUNKS; c++) {
        int idx = (b * CHUNKS + c) * Dsz + e;
        g_h0[idx] = h;
        h = fmaf(g_P[idx], h, g_S[idx]);
    }
}

__global__ void scan_apply(float* __restrict__ out) {
    int g = blockIdx.x * blockDim.x + threadIdx.x;
    int e = g & (Dsz - 1);
    int rest = g >> 10;
    int c = rest & (CHUNKS - 1);
    int b = rest >> 5;
    size_t base = ((size_t)(b * Tsz + c * CLEN)) * Dsz + e;
    float h = g_h0[(b * CHUNKS + c) * Dsz + e];
    #pragma unroll 4
    for (int t = 0; t < CLEN; t++) {
        float a  = g_a[base + (size_t)t * Dsz];
        float bp = g_b[base + (size_t)t * Dsz];
        float bb = sqrtf(fmaxf(1.f - a * a, 0.f)) * bp;
        h = fmaf(a, h, bb);
        out[base + (size_t)t * Dsz] = h;
    }
}

// ---------------- launch --------------------------------------------------------
extern "C" void kernel_launch(void* const* d_in, const int* in_sizes, int n_in,
                              void* d_out, int out_size) {
    (void)in_sizes; (void)n_in; (void)out_size;
    const float* x     = (const float*)d_in[0];
    const float* Wr    = (const float*)d_in[1];
    const float* Wi    = (const float*)d_in[2];
    const float* lambd = (const float*)d_in[3];
    float* out = (float*)d_out;

    static bool attr_set = false;
    if (!attr_set) {
        cudaFuncSetAttribute(gemm_tc, cudaFuncAttributeMaxDynamicSharedMemorySize,
                             SMEM_BYTES);
        attr_set = true;
    }

    lsig_kernel<<<4, 256>>>(lambd);
    prep_w<<<Nsz, 256>>>(Wr, Wi);

    dim3 grid(Nsz / BN, Msz / BM);   // (32, 256)
    gemm_tc<<<grid, 256, SMEM_BYTES>>>(x);

    scan_reduce<<<(Bsz * CHUNKS * Dsz) / 256, 256>>>();
    scan_chunks<<<(Bsz * Dsz) / 256, 256>>>();
    scan_apply<<<(Bsz * CHUNKS * Dsz) / 256, 256>>>(out);
}

// round 5
// speedup vs baseline: 2.3895x; 1.0871x over previous
#include <cuda_runtime.h>
#include <cstdint>

#define Bsz 8
#define Tsz 4096
#define Dsz 1024
#define Msz (Bsz*Tsz)          // 32768 rows
#define Nsz 2048               // both gates concatenated
#define CHUNKS 32
#define CLEN (Tsz/CHUNKS)      // 128

#define BM 256
#define BN 128
#define BK 32
#define NSTAGE 3
#define APAD 36                // smem row stride in floats (conflict-free)
#define A_FLOATS (BM*APAD)     // 9216
#define B_FLOATS (BN*APAD)     // 4608
#define STAGE_FLOATS (A_FLOATS + B_FLOATS)   // 13824
#define SMEM_BYTES (NSTAGE*STAGE_FLOATS*4)   // 165888

// ---------------- scratch ----------------------------------------------------
__device__ float g_a  [(size_t)Msz*Dsz];      // a gate (128 MB)
__device__ float g_b  [(size_t)Msz*Dsz];      // b' = sigmoid(zi)*x (128 MB)
__device__ float g_wc [(size_t)Nsz*Dsz];      // tf32-rounded [Wr; Wi] (8 MB)
__device__ float g_lsig[Dsz];
__device__ float g_P[Bsz*CHUNKS*Dsz];
__device__ float g_S[Bsz*CHUNKS*Dsz];
__device__ float g_h0[Bsz*CHUNKS*Dsz];

// ---------------- helpers -----------------------------------------------------
__device__ __forceinline__ uint32_t smem_u32(const void* p) {
    uint32_t a;
    asm("{ .reg .u64 t; cvta.to.shared.u64 t, %1; cvt.u32.u64 %0, t; }"
        : "=r"(a) : "l"(p));
    return a;
}
__device__ __forceinline__ void cp16(uint32_t saddr, const void* gaddr) {
    asm volatile("cp.async.cg.shared.global [%0], [%1], 16;"
                 :: "r"(saddr), "l"(gaddr));
}
__device__ __forceinline__ float tf32_rn(float v) {
    uint32_t o;
    asm("cvt.rn.tf32.f32 %0, %1;" : "=r"(o) : "f"(v));
    return __uint_as_float(o);
}
__device__ __forceinline__ void mma_tf32(float* d, const uint32_t* a, const uint32_t* b) {
    asm volatile(
        "mma.sync.aligned.m16n8k8.row.col.f32.tf32.tf32.f32 "
        "{%0,%1,%2,%3}, {%4,%5,%6,%7}, {%8,%9}, {%0,%1,%2,%3};"
        : "+f"(d[0]), "+f"(d[1]), "+f"(d[2]), "+f"(d[3])
        : "r"(a[0]), "r"(a[1]), "r"(a[2]), "r"(a[3]), "r"(b[0]), "r"(b[1]));
}

// ---------------- prep kernels -------------------------------------------------
__global__ void lsig_kernel(const float* __restrict__ lambd) {
    int i = blockIdx.x * blockDim.x + threadIdx.x;
    if (i < Dsz) g_lsig[i] = -log1pf(expf(-lambd[i]));
}
__global__ void prep_w(const float* __restrict__ wr, const float* __restrict__ wi) {
    int row = blockIdx.x;                      // 0..2047
    const float* src = (row < Dsz) ? (wr + (size_t)row * Dsz)
                                   : (wi + (size_t)(row - Dsz) * Dsz);
    float* dst = g_wc + (size_t)row * Dsz;
    int c = threadIdx.x * 4;
    float4 v = *(const float4*)(src + c);
    *(float4*)(dst + c) = make_float4(tf32_rn(v.x), tf32_rn(v.y), tf32_rn(v.z), tf32_rn(v.w));
}

// ---------------- GEMM (tf32 mma.sync, 64x64 warp tile) ------------------------
__global__ __launch_bounds__(256, 1)
void gemm_tc(const float* __restrict__ x) {
    extern __shared__ __align__(16) float sm[];
    const int tid = threadIdx.x;
    const int wid = tid >> 5, l = tid & 31;
    const int gq  = l >> 2, tq = l & 3;
    const int warp_m = wid & 3;             // 4 groups x 64 rows
    const int warp_n = wid >> 2;            // 2 groups x 64 cols
    const int m0 = blockIdx.y * BM;
    const int n0 = blockIdx.x * BN;

    float acc[4][8][4];
    #pragma unroll
    for (int mt = 0; mt < 4; mt++)
        #pragma unroll
        for (int nt = 0; nt < 8; nt++)
            #pragma unroll
            for (int q = 0; q < 4; q++) acc[mt][nt][q] = 0.f;

    const uint32_t s0 = smem_u32(sm);

    auto load_stage = [&](int st, int k0) {
        uint32_t sA = s0 + st * STAGE_FLOATS * 4;
        uint32_t sB = sA + A_FLOATS * 4;
        const float* ag = x + (size_t)m0 * Dsz + k0 * BK;
        #pragma unroll
        for (int i = 0; i < 8; i++) {            // A: 256 rows x 8 chunks
            int idx = tid + i * 256;
            int r = idx >> 3, c = idx & 7;
            cp16(sA + (r * APAD + c * 4) * 4, ag + (size_t)r * Dsz + c * 4);
        }
        const float* bg = g_wc + (size_t)n0 * Dsz + k0 * BK;
        #pragma unroll
        for (int i = 0; i < 4; i++) {            // B: 128 rows x 8 chunks
            int idx = tid + i * 256;
            int r = idx >> 3, c = idx & 7;
            cp16(sB + (r * APAD + c * 4) * 4, bg + (size_t)r * Dsz + c * 4);
        }
        asm volatile("cp.async.commit_group;" ::: "memory");
    };

    load_stage(0, 0);
    load_stage(1, 1);

    #pragma unroll 1
    for (int k0 = 0; k0 < Dsz / BK; k0++) {
        int s = k0 % NSTAGE;
        if (k0 < Dsz / BK - 1)
            asm volatile("cp.async.wait_group 1;" ::: "memory");
        else
            asm volatile("cp.async.wait_group 0;" ::: "memory");
        __syncthreads();

        const float* As = sm + s * STAGE_FLOATS;
        const float* Bs = As + A_FLOATS;
        #pragma unroll
        for (int kk = 0; kk < 4; kk++) {
            int kb = kk * 8 + tq;
            uint32_t af[4][4], bf[8][2];
            #pragma unroll
            for (int mt = 0; mt < 4; mt++) {
                const float* ap = As + (warp_m * 64 + mt * 16 + gq) * APAD + kb;
                af[mt][0] = __float_as_uint(ap[0]);
                af[mt][1] = __float_as_uint(ap[8 * APAD]);
                af[mt][2] = __float_as_uint(ap[4]);
                af[mt][3] = __float_as_uint(ap[8 * APAD + 4]);
            }
            #pragma unroll
            for (int nt = 0; nt < 8; nt++) {
                const float* bp = Bs + (warp_n * 64 + nt * 8 + gq) * APAD + kb;
                bf[nt][0] = __float_as_uint(bp[0]);
                bf[nt][1] = __float_as_uint(bp[4]);
            }
            #pragma unroll
            for (int mt = 0; mt < 4; mt++)
                #pragma unroll
                for (int nt = 0; nt < 8; nt++)
                    mma_tf32(acc[mt][nt], af[mt], bf[nt]);
        }
        if (k0 + 2 < Dsz / BK) load_stage((k0 + 2) % NSTAGE, k0 + 2);
    }

    // --- epilogue ---
    const bool is_r = (n0 < Dsz);
    #pragma unroll
    for (int mt = 0; mt < 4; mt++) {
        #pragma unroll
        for (int nt = 0; nt < 8; nt++) {
            int col = n0 + warp_n * 64 + nt * 8 + 2 * tq;
            #pragma unroll
            for (int h = 0; h < 2; h++) {
                int row = m0 + warp_m * 64 + mt * 16 + gq + 8 * h;
                float z0 = acc[mt][nt][2 * h + 0];
                float z1 = acc[mt][nt][2 * h + 1];
                if (is_r) {
                    float ls0 = __ldg(&g_lsig[col]);
                    float ls1 = __ldg(&g_lsig[col + 1]);
                    float r0 = __fdividef(1.f, 1.f + __expf(-z0));
                    float r1 = __fdividef(1.f, 1.f + __expf(-z1));
                    float2 av = make_float2(__expf(8.f * r0 * ls0),
                                            __expf(8.f * r1 * ls1));
                    *(float2*)(g_a + (size_t)row * Dsz + col) = av;
                } else {
                    int ce = col - Dsz;
                    float2 xv = *(const float2*)(x + (size_t)row * Dsz + ce);
                    float i0 = __fdividef(1.f, 1.f + __expf(-z0));
                    float i1 = __fdividef(1.f, 1.f + __expf(-z1));
                    float2 bv = make_float2(i0 * xv.x, i1 * xv.y);
                    *(float2*)(g_b + (size_t)row * Dsz + ce) = bv;
                }
            }
        }
    }
}

// ---------------- scan kernels (float4 vectorized) ------------------------------
__global__ void scan_reduce() {
    int g = blockIdx.x * blockDim.x + threadIdx.x;   // 65536 threads
    int e4 = g & (Dsz / 4 - 1);
    int rest = g >> 8;
    int c = rest & (CHUNKS - 1);
    int b = rest >> 5;
    size_t base = ((size_t)(b * Tsz + c * CLEN)) * Dsz + e4 * 4;
    float4 P = make_float4(1.f, 1.f, 1.f, 1.f);
    float4 H = make_float4(0.f, 0.f, 0.f, 0.f);
    #pragma unroll 4
    for (int t = 0; t < CLEN; t++) {
        float4 a  = *(const float4*)(g_a + base + (size_t)t * Dsz);
        float4 bp = *(const float4*)(g_b + base + (size_t)t * Dsz);
        H.x = fmaf(a.x, H.x, sqrtf(fmaxf(1.f - a.x*a.x, 0.f)) * bp.x);
        H.y = fmaf(a.y, H.y, sqrtf(fmaxf(1.f - a.y*a.y, 0.f)) * bp.y);
        H.z = fmaf(a.z, H.z, sqrtf(fmaxf(1.f - a.z*a.z, 0.f)) * bp.z);
        H.w = fmaf(a.w, H.w, sqrtf(fmaxf(1.f - a.w*a.w, 0.f)) * bp.w);
        P.x *= a.x; P.y *= a.y; P.z *= a.z; P.w *= a.w;
    }
    size_t idx = ((size_t)(b * CHUNKS + c) * Dsz) + e4 * 4;
    *(float4*)(g_P + idx) = P;
    *(float4*)(g_S + idx) = H;
}

__global__ void scan_chunks() {
    int g = blockIdx.x * blockDim.x + threadIdx.x;   // 2048 threads
    int e4 = g & (Dsz / 4 - 1);
    int b = g >> 8;
    float4 h = make_float4(0.f, 0.f, 0.f, 0.f);
    #pragma unroll
    for (int c = 0; c < CHUNKS; c++) {
        size_t idx = ((size_t)(b * CHUNKS + c) * Dsz) + e4 * 4;
        *(float4*)(g_h0 + idx) = h;
        float4 P = *(const float4*)(g_P + idx);
        float4 S = *(const float4*)(g_S + idx);
        h.x = fmaf(P.x, h.x, S.x);
        h.y = fmaf(P.y, h.y, S.y);
        h.z = fmaf(P.z, h.z, S.z);
        h.w = fmaf(P.w, h.w, S.w);
    }
}

__global__ void scan_apply(float* __restrict__ out) {
    int g = blockIdx.x * blockDim.x + threadIdx.x;   // 65536 threads
    int e4 = g & (Dsz / 4 - 1);
    int rest = g >> 8;
    int c = rest & (CHUNKS - 1);
    int b = rest >> 5;
    size_t base = ((size_t)(b * Tsz + c * CLEN)) * Dsz + e4 * 4;
    float4 h = *(const float4*)(g_h0 + ((size_t)(b * CHUNKS + c) * Dsz) + e4 * 4);
    #pragma unroll 4
    for (int t = 0; t < CLEN; t++) {
        float4 a  = *(const float4*)(g_a + base + (size_t)t * Dsz);
        float4 bp = *(const float4*)(g_b + base + (size_t)t * Dsz);
        h.x = fmaf(a.x, h.x, sqrtf(fmaxf(1.f - a.x*a.x, 0.f)) * bp.x);
        h.y = fmaf(a.y, h.y, sqrtf(fmaxf(1.f - a.y*a.y, 0.f)) * bp.y);
        h.z = fmaf(a.z, h.z, sqrtf(fmaxf(1.f - a.z*a.z, 0.f)) * bp.z);
        h.w = fmaf(a.w, h.w, sqrtf(fmaxf(1.f - a.w*a.w, 0.f)) * bp.w);
        *(float4*)(out + base + (size_t)t * Dsz) = h;
    }
}

// ---------------- launch --------------------------------------------------------
extern "C" void kernel_launch(void* const* d_in, const int* in_sizes, int n_in,
                              void* d_out, int out_size) {
    (void)in_sizes; (void)n_in; (void)out_size;
    const float* x     = (const float*)d_in[0];
    const float* Wr    = (const float*)d_in[1];
    const float* Wi    = (const float*)d_in[2];
    const float* lambd = (const float*)d_in[3];
    float* out = (float*)d_out;

    static bool attr_set = false;
    if (!attr_set) {
        cudaFuncSetAttribute(gemm_tc, cudaFuncAttributeMaxDynamicSharedMemorySize,
                             SMEM_BYTES);
        attr_set = true;
    }

    lsig_kernel<<<4, 256>>>(lambd);
    prep_w<<<Nsz, 256>>>(Wr, Wi);

    dim3 grid(Nsz / BN, Msz / BM);   // (16, 128) = 2048 CTAs
    gemm_tc<<<grid, 256, SMEM_BYTES>>>(x);

    scan_reduce<<<512, 128>>>();
    scan_chunks<<<16, 128>>>();
    scan_apply<<<512, 128>>>(out);
}

// round 6
// speedup vs baseline: 3.0156x; 1.2620x over previous
#include <cuda_runtime.h>
#include <cuda_fp16.h>
#include <cstdint>

#define Bsz 8
#define Tsz 4096
#define Dsz 1024
#define Msz (Bsz*Tsz)          // 32768 rows
#define Nsz 2048               // both gates concatenated
#define CHUNKS 32
#define CLEN (Tsz/CHUNKS)      // 128

#define BM 256
#define BN 128
#define BK 32
#define NSTAGE 4
#define APAD_B 80                          // smem row stride in BYTES (40 halves)
#define A_BYTES (BM*APAD_B)                // 20480
#define B_BYTES (BN*APAD_B)                // 10240
#define STAGE_BYTES (A_BYTES + B_BYTES)    // 30720
#define SMEM_BYTES (NSTAGE*STAGE_BYTES)    // 122880

// ---------------- scratch ----------------------------------------------------
__device__ float  g_a [(size_t)Msz*Dsz];      // a gate (128 MB)
__device__ float  g_b [(size_t)Msz*Dsz];      // b' = sigmoid(zi)*x (128 MB)
__device__ __half g_xh[(size_t)Msz*Dsz];      // fp16 x (64 MB)
__device__ __half g_wh[(size_t)Nsz*Dsz];      // fp16 [Wr; Wi] (4 MB)
__device__ float  g_lsig[Dsz];
__device__ float  g_P[Bsz*CHUNKS*Dsz];
__device__ float  g_S[Bsz*CHUNKS*Dsz];
__device__ float  g_h0[Bsz*CHUNKS*Dsz];

// ---------------- helpers -----------------------------------------------------
__device__ __forceinline__ uint32_t smem_u32(const void* p) {
    uint32_t a;
    asm("{ .reg .u64 t; cvta.to.shared.u64 t, %1; cvt.u32.u64 %0, t; }"
        : "=r"(a) : "l"(p));
    return a;
}
__device__ __forceinline__ void cp16(uint32_t saddr, const void* gaddr) {
    asm volatile("cp.async.cg.shared.global [%0], [%1], 16;"
                 :: "r"(saddr), "l"(gaddr));
}
__device__ __forceinline__ void mma_f16(float* d, const uint32_t* a, const uint32_t* b) {
    asm volatile(
        "mma.sync.aligned.m16n8k16.row.col.f32.f16.f16.f32 "
        "{%0,%1,%2,%3}, {%4,%5,%6,%7}, {%8,%9}, {%0,%1,%2,%3};"
        : "+f"(d[0]), "+f"(d[1]), "+f"(d[2]), "+f"(d[3])
        : "r"(a[0]), "r"(a[1]), "r"(a[2]), "r"(a[3]), "r"(b[0]), "r"(b[1]));
}
__device__ __forceinline__ uint32_t lds32(uint32_t addr) {
    uint32_t v;
    asm volatile("ld.shared.b32 %0, [%1];" : "=r"(v) : "r"(addr));
    return v;
}

// ---------------- prep kernels -------------------------------------------------
__global__ void lsig_kernel(const float* __restrict__ lambd) {
    int i = blockIdx.x * blockDim.x + threadIdx.x;
    if (i < Dsz) g_lsig[i] = -log1pf(expf(-lambd[i]));
}
__global__ void prep_x(const float* __restrict__ x) {
    size_t i = ((size_t)blockIdx.x * 256 + threadIdx.x) * 4;
    float4 v = *(const float4*)(x + i);
    __half2 h0 = __floats2half2_rn(v.x, v.y);
    __half2 h1 = __floats2half2_rn(v.z, v.w);
    uint2 u;
    u.x = *(uint32_t*)&h0;
    u.y = *(uint32_t*)&h1;
    *(uint2*)(g_xh + i) = u;
}
__global__ void prep_w(const float* __restrict__ wr, const float* __restrict__ wi) {
    int row = blockIdx.x;                      // 0..2047
    const float* src = (row < Dsz) ? (wr + (size_t)row * Dsz)
                                   : (wi + (size_t)(row - Dsz) * Dsz);
    __half* dst = g_wh + (size_t)row * Dsz;
    int c = threadIdx.x * 4;
    float4 v = *(const float4*)(src + c);
    __half2 h0 = __floats2half2_rn(v.x, v.y);
    __half2 h1 = __floats2half2_rn(v.z, v.w);
    uint2 u;
    u.x = *(uint32_t*)&h0;
    u.y = *(uint32_t*)&h1;
    *(uint2*)(dst + c) = u;
}

// ---------------- GEMM (fp16 mma.sync m16n8k16, 64x64 warp tile) ----------------
__global__ __launch_bounds__(256, 1)
void gemm_tc(const float* __restrict__ x) {
    extern __shared__ __align__(16) char sm[];
    const int tid = threadIdx.x;
    const int wid = tid >> 5, l = tid & 31;
    const int gq  = l >> 2, tq = l & 3;
    const int warp_m = wid & 3;             // 4 groups x 64 rows
    const int warp_n = wid >> 2;            // 2 groups x 64 cols
    const int m0 = blockIdx.y * BM;
    const int n0 = blockIdx.x * BN;

    float acc[4][8][4];
    #pragma unroll
    for (int mt = 0; mt < 4; mt++)
        #pragma unroll
        for (int nt = 0; nt < 8; nt++)
            #pragma unroll
            for (int q = 0; q < 4; q++) acc[mt][nt][q] = 0.f;

    const uint32_t s0 = smem_u32(sm);

    auto load_stage = [&](int st, int k0) {
        uint32_t sA = s0 + st * STAGE_BYTES;
        uint32_t sB = sA + A_BYTES;
        const __half* ag = g_xh + (size_t)m0 * Dsz + k0 * BK;
        #pragma unroll
        for (int i = 0; i < 4; i++) {            // A: 256 rows x 4 chunks of 16B
            int idx = tid + i * 256;
            int r = idx >> 2, c = idx & 3;
            cp16(sA + r * APAD_B + c * 16, ag + (size_t)r * Dsz + c * 8);
        }
        const __half* bg = g_wh + (size_t)n0 * Dsz + k0 * BK;
        #pragma unroll
        for (int i = 0; i < 2; i++) {            // B: 128 rows x 4 chunks of 16B
            int idx = tid + i * 256;
            int r = idx >> 2, c = idx & 3;
            cp16(sB + r * APAD_B + c * 16, bg + (size_t)r * Dsz + c * 8);
        }
        asm volatile("cp.async.commit_group;" ::: "memory");
    };

    load_stage(0, 0);
    load_stage(1, 1);
    load_stage(2, 2);

    #pragma unroll 1
    for (int k0 = 0; k0 < Dsz / BK; k0++) {
        int s = k0 % NSTAGE;
        if (k0 < Dsz / BK - 2)
            asm volatile("cp.async.wait_group 2;" ::: "memory");
        else if (k0 == Dsz / BK - 2)
            asm volatile("cp.async.wait_group 1;" ::: "memory");
        else
            asm volatile("cp.async.wait_group 0;" ::: "memory");
        __syncthreads();

        uint32_t As = s0 + s * STAGE_BYTES;
        uint32_t Bs = As + A_BYTES;
        #pragma unroll
        for (int kk = 0; kk < 2; kk++) {         // K=16 each
            uint32_t kb = kk * 32 + tq * 4;      // byte offset within row
            uint32_t af[4][4], bf[8][2];
            #pragma unroll
            for (int mt = 0; mt < 4; mt++) {
                uint32_t ap = As + (warp_m * 64 + mt * 16 + gq) * APAD_B + kb;
                af[mt][0] = lds32(ap);
                af[mt][1] = lds32(ap + 8 * APAD_B);
                af[mt][2] = lds32(ap + 16);
                af[mt][3] = lds32(ap + 8 * APAD_B + 16);
            }
            #pragma unroll
            for (int nt = 0; nt < 8; nt++) {
                uint32_t bp = Bs + (warp_n * 64 + nt * 8 + gq) * APAD_B + kb;
                bf[nt][0] = lds32(bp);
                bf[nt][1] = lds32(bp + 16);
            }
            #pragma unroll
            for (int mt = 0; mt < 4; mt++)
                #pragma unroll
                for (int nt = 0; nt < 8; nt++)
                    mma_f16(acc[mt][nt], af[mt], bf[nt]);
        }
        if (k0 + 3 < Dsz / BK) load_stage((k0 + 3) % NSTAGE, k0 + 3);
    }

    // --- epilogue ---
    const bool is_r = (n0 < Dsz);
    #pragma unroll
    for (int mt = 0; mt < 4; mt++) {
        #pragma unroll
        for (int nt = 0; nt < 8; nt++) {
            int col = n0 + warp_n * 64 + nt * 8 + 2 * tq;
            #pragma unroll
            for (int h = 0; h < 2; h++) {
                int row = m0 + warp_m * 64 + mt * 16 + gq + 8 * h;
                float z0 = acc[mt][nt][2 * h + 0];
                float z1 = acc[mt][nt][2 * h + 1];
                if (is_r) {
                    float ls0 = __ldg(&g_lsig[col]);
                    float ls1 = __ldg(&g_lsig[col + 1]);
                    float r0 = __fdividef(1.f, 1.f + __expf(-z0));
                    float r1 = __fdividef(1.f, 1.f + __expf(-z1));
                    float2 av = make_float2(__expf(8.f * r0 * ls0),
                                            __expf(8.f * r1 * ls1));
                    *(float2*)(g_a + (size_t)row * Dsz + col) = av;
                } else {
                    int ce = col - Dsz;
                    float2 xv = *(const float2*)(x + (size_t)row * Dsz + ce);
                    float i0 = __fdividef(1.f, 1.f + __expf(-z0));
                    float i1 = __fdividef(1.f, 1.f + __expf(-z1));
                    float2 bv = make_float2(i0 * xv.x, i1 * xv.y);
                    *(float2*)(g_b + (size_t)row * Dsz + ce) = bv;
                }
            }
        }
    }
}

// ---------------- scan kernels (scalar, 1 thread / channel) ---------------------
__global__ void scan_reduce() {
    int g = blockIdx.x * blockDim.x + threadIdx.x;   // 262144 threads
    int e = g & (Dsz - 1);
    int rest = g >> 10;
    int c = rest & (CHUNKS - 1);
    int b = rest >> 5;
    size_t base = ((size_t)(b * Tsz + c * CLEN)) * Dsz + e;
    float P = 1.f, H = 0.f;
    #pragma unroll 4
    for (int t = 0; t < CLEN; t++) {
        float a  = __ldcs(g_a + base + (size_t)t * Dsz);
        float bp = __ldcs(g_b + base + (size_t)t * Dsz);
        float bb = sqrtf(fmaxf(1.f - a * a, 0.f)) * bp;
        H = fmaf(a, H, bb);
        P *= a;
    }
    int idx = (b * CHUNKS + c) * Dsz + e;
    g_P[idx] = P;
    g_S[idx] = H;
}

__global__ void scan_chunks() {
    int g = blockIdx.x * blockDim.x + threadIdx.x;   // 8192 threads
    int e = g & (Dsz - 1);
    int b = g >> 10;
    float h = 0.f;
    #pragma unroll
    for (int c = 0; c < CHUNKS; c++) {
        int idx = (b * CHUNKS + c) * Dsz + e;
        g_h0[idx] = h;
        h = fmaf(g_P[idx], h, g_S[idx]);
    }
}

__global__ void scan_apply(float* __restrict__ out) {
    int g = blockIdx.x * blockDim.x + threadIdx.x;
    int e = g & (Dsz - 1);
    int rest = g >> 10;
    int c = rest & (CHUNKS - 1);
    int b = rest >> 5;
    size_t base = ((size_t)(b * Tsz + c * CLEN)) * Dsz + e;
    float h = g_h0[(b * CHUNKS + c) * Dsz + e];
    #pragma unroll 4
    for (int t = 0; t < CLEN; t++) {
        float a  = __ldcs(g_a + base + (size_t)t * Dsz);
        float bp = __ldcs(g_b + base + (size_t)t * Dsz);
        float bb = sqrtf(fmaxf(1.f - a * a, 0.f)) * bp;
        h = fmaf(a, h, bb);
        out[base + (size_t)t * Dsz] = h;
    }
}

// ---------------- launch --------------------------------------------------------
extern "C" void kernel_launch(void* const* d_in, const int* in_sizes, int n_in,
                              void* d_out, int out_size) {
    (void)in_sizes; (void)n_in; (void)out_size;
    const float* x     = (const float*)d_in[0];
    const float* Wr    = (const float*)d_in[1];
    const float* Wi    = (const float*)d_in[2];
    const float* lambd = (const float*)d_in[3];
    float* out = (float*)d_out;

    static bool attr_set = false;
    if (!attr_set) {
        cudaFuncSetAttribute(gemm_tc, cudaFuncAttributeMaxDynamicSharedMemorySize,
                             SMEM_BYTES);
        attr_set = true;
    }

    lsig_kernel<<<4, 256>>>(lambd);
    prep_x<<<(Msz * Dsz) / 1024, 256>>>(x);
    prep_w<<<Nsz, 256>>>(Wr, Wi);

    dim3 grid(Nsz / BN, Msz / BM);   // (16, 128) = 2048 CTAs
    gemm_tc<<<grid, 256, SMEM_BYTES>>>(x);

    scan_reduce<<<(Bsz * CHUNKS * Dsz) / 256, 256>>>();
    scan_chunks<<<(Bsz * Dsz) / 256, 256>>>();
    scan_apply<<<(Bsz * CHUNKS * Dsz) / 256, 256>>>(out);
}

// round 7
// speedup vs baseline: 3.2467x; 1.0766x over previous
#include <cuda_runtime.h>
#include <cuda_fp16.h>
#include <cstdint>

#define Bsz 8
#define Tsz 4096
#define Dsz 1024
#define Msz (Bsz*Tsz)          // 32768 rows
#define Nsz 2048               // both gates concatenated
#define CHUNKS 32
#define CLEN (Tsz/CHUNKS)      // 128

#define BM 256
#define BN 128
#define BK 32
#define NTHREADS 512
#define NSTAGE 4
#define APAD_B 80                          // smem row stride in BYTES (40 halves)
#define A_BYTES (BM*APAD_B)                // 20480
#define B_BYTES (BN*APAD_B)                // 10240
#define STAGE_BYTES (A_BYTES + B_BYTES)    // 30720
#define SMEM_BYTES (NSTAGE*STAGE_BYTES)    // 122880

// ---------------- scratch ----------------------------------------------------
__device__ float  g_a [(size_t)Msz*Dsz];      // a gate (128 MB)
__device__ float  g_b [(size_t)Msz*Dsz];      // b' = sigmoid(zi)*x (128 MB)
__device__ __half g_xh[(size_t)Msz*Dsz];      // fp16 x (64 MB)
__device__ __half g_wh[(size_t)Nsz*Dsz];      // fp16 [Wr; Wi] (4 MB)
__device__ float  g_lsig[Dsz];
__device__ float  g_P[Bsz*CHUNKS*Dsz];
__device__ float  g_S[Bsz*CHUNKS*Dsz];
__device__ float  g_h0[Bsz*CHUNKS*Dsz];

// ---------------- helpers -----------------------------------------------------
__device__ __forceinline__ uint32_t smem_u32(const void* p) {
    uint32_t a;
    asm("{ .reg .u64 t; cvta.to.shared.u64 t, %1; cvt.u32.u64 %0, t; }"
        : "=r"(a) : "l"(p));
    return a;
}
__device__ __forceinline__ void cp16(uint32_t saddr, const void* gaddr) {
    asm volatile("cp.async.cg.shared.global [%0], [%1], 16;"
                 :: "r"(saddr), "l"(gaddr));
}
__device__ __forceinline__ void mma_f16(float* d, const uint32_t* a, const uint32_t* b) {
    asm volatile(
        "mma.sync.aligned.m16n8k16.row.col.f32.f16.f16.f32 "
        "{%0,%1,%2,%3}, {%4,%5,%6,%7}, {%8,%9}, {%0,%1,%2,%3};"
        : "+f"(d[0]), "+f"(d[1]), "+f"(d[2]), "+f"(d[3])
        : "r"(a[0]), "r"(a[1]), "r"(a[2]), "r"(a[3]), "r"(b[0]), "r"(b[1]));
}
__device__ __forceinline__ uint32_t lds32(uint32_t addr) {
    uint32_t v;
    asm volatile("ld.shared.b32 %0, [%1];" : "=r"(v) : "r"(addr));
    return v;
}

// ---------------- prep kernels -------------------------------------------------
__global__ void lsig_kernel(const float* __restrict__ lambd) {
    int i = blockIdx.x * blockDim.x + threadIdx.x;
    if (i < Dsz) g_lsig[i] = -log1pf(expf(-lambd[i]));
}
__global__ void prep_x(const float* __restrict__ x) {
    size_t i = ((size_t)blockIdx.x * 256 + threadIdx.x) * 4;
    float4 v = *(const float4*)(x + i);
    __half2 h0 = __floats2half2_rn(v.x, v.y);
    __half2 h1 = __floats2half2_rn(v.z, v.w);
    uint2 u;
    u.x = *(uint32_t*)&h0;
    u.y = *(uint32_t*)&h1;
    *(uint2*)(g_xh + i) = u;
}
__global__ void prep_w(const float* __restrict__ wr, const float* __restrict__ wi) {
    int row = blockIdx.x;                      // 0..2047
    const float* src = (row < Dsz) ? (wr + (size_t)row * Dsz)
                                   : (wi + (size_t)(row - Dsz) * Dsz);
    __half* dst = g_wh + (size_t)row * Dsz;
    int c = threadIdx.x * 4;
    float4 v = *(const float4*)(src + c);
    __half2 h0 = __floats2half2_rn(v.x, v.y);
    __half2 h1 = __floats2half2_rn(v.z, v.w);
    uint2 u;
    u.x = *(uint32_t*)&h0;
    u.y = *(uint32_t*)&h1;
    *(uint2*)(dst + c) = u;
}

// ---------------- GEMM (fp16 mma.sync m16n8k16, 16 warps, 64x32 warp tile) ------
__global__ __launch_bounds__(NTHREADS, 1)
void gemm_tc(const float* __restrict__ x) {
    extern __shared__ __align__(16) char sm[];
    const int tid = threadIdx.x;
    const int wid = tid >> 5, l = tid & 31;
    const int gq  = l >> 2, tq = l & 3;
    const int warp_m = wid & 3;             // 4 groups x 64 rows
    const int warp_n = wid >> 2;            // 4 groups x 32 cols
    const int m0 = blockIdx.y * BM;
    const int n0 = blockIdx.x * BN;

    float acc[4][4][4];
    #pragma unroll
    for (int mt = 0; mt < 4; mt++)
        #pragma unroll
        for (int nt = 0; nt < 4; nt++)
            #pragma unroll
            for (int q = 0; q < 4; q++) acc[mt][nt][q] = 0.f;

    const uint32_t s0 = smem_u32(sm);

    auto load_stage = [&](int st, int k0) {
        uint32_t sA = s0 + st * STAGE_BYTES;
        uint32_t sB = sA + A_BYTES;
        const __half* ag = g_xh + (size_t)m0 * Dsz + k0 * BK;
        #pragma unroll
        for (int i = 0; i < 2; i++) {            // A: 256 rows x 4 chunks of 16B
            int idx = tid + i * NTHREADS;
            int r = idx >> 2, c = idx & 3;
            cp16(sA + r * APAD_B + c * 16, ag + (size_t)r * Dsz + c * 8);
        }
        {                                        // B: 128 rows x 4 chunks of 16B
            int r = tid >> 2, c = tid & 3;
            cp16(sB + r * APAD_B + c * 16,
                 g_wh + (size_t)(n0 + r) * Dsz + k0 * BK + c * 8);
        }
        asm volatile("cp.async.commit_group;" ::: "memory");
    };

    load_stage(0, 0);
    load_stage(1, 1);
    load_stage(2, 2);

    #pragma unroll 1
    for (int k0 = 0; k0 < Dsz / BK; k0++) {
        int s = k0 % NSTAGE;
        if (k0 < Dsz / BK - 2)
            asm volatile("cp.async.wait_group 2;" ::: "memory");
        else if (k0 == Dsz / BK - 2)
            asm volatile("cp.async.wait_group 1;" ::: "memory");
        else
            asm volatile("cp.async.wait_group 0;" ::: "memory");
        __syncthreads();

        uint32_t As = s0 + s * STAGE_BYTES;
        uint32_t Bs = As + A_BYTES;
        #pragma unroll
        for (int kk = 0; kk < 2; kk++) {         // K=16 each
            uint32_t kb = kk * 32 + tq * 4;      // byte offset within row
            uint32_t af[4][4], bf[4][2];
            #pragma unroll
            for (int mt = 0; mt < 4; mt++) {
                uint32_t ap = As + (warp_m * 64 + mt * 16 + gq) * APAD_B + kb;
                af[mt][0] = lds32(ap);
                af[mt][1] = lds32(ap + 8 * APAD_B);
                af[mt][2] = lds32(ap + 16);
                af[mt][3] = lds32(ap + 8 * APAD_B + 16);
            }
            #pragma unroll
            for (int nt = 0; nt < 4; nt++) {
                uint32_t bp = Bs + (warp_n * 32 + nt * 8 + gq) * APAD_B + kb;
                bf[nt][0] = lds32(bp);
                bf[nt][1] = lds32(bp + 16);
            }
            #pragma unroll
            for (int mt = 0; mt < 4; mt++)
                #pragma unroll
                for (int nt = 0; nt < 4; nt++)
                    mma_f16(acc[mt][nt], af[mt], bf[nt]);
        }
        if (k0 + 3 < Dsz / BK) load_stage((k0 + 3) % NSTAGE, k0 + 3);
    }

    // --- epilogue ---
    const bool is_r = (n0 < Dsz);
    #pragma unroll
    for (int mt = 0; mt < 4; mt++) {
        #pragma unroll
        for (int nt = 0; nt < 4; nt++) {
            int col = n0 + warp_n * 32 + nt * 8 + 2 * tq;
            #pragma unroll
            for (int h = 0; h < 2; h++) {
                int row = m0 + warp_m * 64 + mt * 16 + gq + 8 * h;
                float z0 = acc[mt][nt][2 * h + 0];
                float z1 = acc[mt][nt][2 * h + 1];
                if (is_r) {
                    float ls0 = __ldg(&g_lsig[col]);
                    float ls1 = __ldg(&g_lsig[col + 1]);
                    float r0 = __fdividef(1.f, 1.f + __expf(-z0));
                    float r1 = __fdividef(1.f, 1.f + __expf(-z1));
                    float2 av = make_float2(__expf(8.f * r0 * ls0),
                                            __expf(8.f * r1 * ls1));
                    *(float2*)(g_a + (size_t)row * Dsz + col) = av;
                } else {
                    int ce = col - Dsz;
                    float2 xv = *(const float2*)(x + (size_t)row * Dsz + ce);
                    float i0 = __fdividef(1.f, 1.f + __expf(-z0));
                    float i1 = __fdividef(1.f, 1.f + __expf(-z1));
                    float2 bv = make_float2(i0 * xv.x, i1 * xv.y);
                    *(float2*)(g_b + (size_t)row * Dsz + ce) = bv;
                }
            }
        }
    }
}

// ---------------- scan kernels (scalar, 1 thread / channel) ---------------------
__global__ void scan_reduce() {
    int g = blockIdx.x * blockDim.x + threadIdx.x;   // 262144 threads
    int e = g & (Dsz - 1);
    int rest = g >> 10;
    int c = rest & (CHUNKS - 1);
    int b = rest >> 5;
    size_t base = ((size_t)(b * Tsz + c * CLEN)) * Dsz + e;
    float P = 1.f, H = 0.f;
    #pragma unroll 4
    for (int t = 0; t < CLEN; t++) {
        float a  = __ldcs(g_a + base + (size_t)t * Dsz);
        float bp = __ldcs(g_b + base + (size_t)t * Dsz);
        float bb = sqrtf(fmaxf(1.f - a * a, 0.f)) * bp;
        H = fmaf(a, H, bb);
        P *= a;
    }
    int idx = (b * CHUNKS + c) * Dsz + e;
    g_P[idx] = P;
    g_S[idx] = H;
}

__global__ void scan_chunks() {
    int g = blockIdx.x * blockDim.x + threadIdx.x;   // 8192 threads
    int e = g & (Dsz - 1);
    int b = g >> 10;
    float h = 0.f;
    #pragma unroll
    for (int c = 0; c < CHUNKS; c++) {
        int idx = (b * CHUNKS + c) * Dsz + e;
        g_h0[idx] = h;
        h = fmaf(g_P[idx], h, g_S[idx]);
    }
}

__global__ void scan_apply(float* __restrict__ out) {
    int g = blockIdx.x * blockDim.x + threadIdx.x;
    int e = g & (Dsz - 1);
    int rest = g >> 10;
    int c = rest & (CHUNKS - 1);
    int b = rest >> 5;
    size_t base = ((size_t)(b * Tsz + c * CLEN)) * Dsz + e;
    float h = g_h0[(b * CHUNKS + c) * Dsz + e];
    #pragma unroll 4
    for (int t = 0; t < CLEN; t++) {
        float a  = __ldcs(g_a + base + (size_t)t * Dsz);
        float bp = __ldcs(g_b + base + (size_t)t * Dsz);
        float bb = sqrtf(fmaxf(1.f - a * a, 0.f)) * bp;
        h = fmaf(a, h, bb);
        out[base + (size_t)t * Dsz] = h;
    }
}

// ---------------- launch --------------------------------------------------------
extern "C" void kernel_launch(void* const* d_in, const int* in_sizes, int n_in,
                              void* d_out, int out_size) {
    (void)in_sizes; (void)n_in; (void)out_size;
    const float* x     = (const float*)d_in[0];
    const float* Wr    = (const float*)d_in[1];
    const float* Wi    = (const float*)d_in[2];
    const float* lambd = (const float*)d_in[3];
    float* out = (float*)d_out;

    static bool attr_set = false;
    if (!attr_set) {
        cudaFuncSetAttribute(gemm_tc, cudaFuncAttributeMaxDynamicSharedMemorySize,
                             SMEM_BYTES);
        attr_set = true;
    }

    lsig_kernel<<<4, 256>>>(lambd);
    prep_x<<<(Msz * Dsz) / 1024, 256>>>(x);
    prep_w<<<Nsz, 256>>>(Wr, Wi);

    dim3 grid(Nsz / BN, Msz / BM);   // (16, 128) = 2048 CTAs
    gemm_tc<<<grid, NTHREADS, SMEM_BYTES>>>(x);

    scan_reduce<<<(Bsz * CHUNKS * Dsz) / 256, 256>>>();
    scan_chunks<<<(Bsz * Dsz) / 256, 256>>>();
    scan_apply<<<(Bsz * CHUNKS * Dsz) / 256, 256>>>(out);
}